// round 16
// baseline (speedup 1.0000x reference)
#include <cuda_runtime.h>
#include <math.h>

#define FEAT    128
#define NRBF    20
#define NATOMS  8192
#define NEDGES  262144
#define NGRAPHS 128
#define APB     8

typedef unsigned long long ull;

// ---------------- f32x2 packed helpers ----------------
__device__ __forceinline__ ull f2pack(float lo, float hi) {
    ull r; asm("mov.b64 %0,{%1,%2};" : "=l"(r) : "f"(lo), "f"(hi)); return r;
}
__device__ __forceinline__ void f2unpack(ull p, float& a, float& b) {
    asm("mov.b64 {%0,%1},%2;" : "=f"(a), "=f"(b) : "l"(p));
}
__device__ __forceinline__ ull f2fma(ull a, ull b, ull c) {
    ull d; asm("fma.rn.f32x2 %0,%1,%2,%3;" : "=l"(d) : "l"(a), "l"(b), "l"(c)); return d;
}
__device__ __forceinline__ ull f2mul(ull a, ull b) {
    ull d; asm("mul.rn.f32x2 %0,%1,%2;" : "=l"(d) : "l"(a), "l"(b)); return d;
}

// ---------------- device scratch ----------------
__device__ float g_phi[NATOMS * 384];
__device__ float g_qkv[NATOMS * 384];
__device__ float g_h  [NATOMS * 128];
__device__ float g_vt [NATOMS * 384];
__device__ int   g_cnt[NATOMS];
__device__ int   g_off[NATOMS];
__device__ int   g_pos[NEDGES];
__device__ int   g_eid[NEDGES];

// ---------------- SGEMM 128x64 tile, 8x4 per thread, f32x2, K=128 -----------
__device__ __forceinline__ void gemm_tile(
    const float* __restrict__ A, const float* __restrict__ B,
    const float* __restrict__ bias, float* __restrict__ C,
    int N, int act, int bx, int by,
    float As[16][132], float Bs[16][68])
{
    const int tid = threadIdx.x;
    const int tx = tid & 15, ty = tid >> 4;
    const int ar = tid >> 1, aq = (tid & 1) * 8;
    const int bk = tid >> 4, bc = (tid & 15) * 4;

    ull acc[8][2];
#pragma unroll
    for (int r = 0; r < 8; r++) { acc[r][0] = 0ull; acc[r][1] = 0ull; }

    for (int k0 = 0; k0 < 128; k0 += 16) {
        __syncthreads();
        {
            float4 a0 = *(const float4*)&A[(size_t)(by + ar) * 128 + k0 + aq];
            float4 a1 = *(const float4*)&A[(size_t)(by + ar) * 128 + k0 + aq + 4];
            As[aq + 0][ar] = a0.x; As[aq + 1][ar] = a0.y;
            As[aq + 2][ar] = a0.z; As[aq + 3][ar] = a0.w;
            As[aq + 4][ar] = a1.x; As[aq + 5][ar] = a1.y;
            As[aq + 6][ar] = a1.z; As[aq + 7][ar] = a1.w;
            *(float4*)&Bs[bk][bc] = *(const float4*)&B[(size_t)(k0 + bk) * N + bx + bc];
        }
        __syncthreads();
#pragma unroll
        for (int kk = 0; kk < 16; kk++) {
            float4 x0 = *(const float4*)&As[kk][ty * 8];
            float4 x1 = *(const float4*)&As[kk][ty * 8 + 4];
            ull b0 = *(const ull*)&Bs[kk][tx * 4];
            ull b1 = *(const ull*)&Bs[kk][tx * 4 + 2];
            float av[8] = {x0.x, x0.y, x0.z, x0.w, x1.x, x1.y, x1.z, x1.w};
#pragma unroll
            for (int r = 0; r < 8; r++) {
                ull s = f2pack(av[r], av[r]);
                acc[r][0] = f2fma(s, b0, acc[r][0]);
                acc[r][1] = f2fma(s, b1, acc[r][1]);
            }
        }
    }
    float b0 = bias[bx + tx * 4], b1 = bias[bx + tx * 4 + 1];
    float b2 = bias[bx + tx * 4 + 2], b3 = bias[bx + tx * 4 + 3];
#pragma unroll
    for (int r = 0; r < 8; r++) {
        float o0, o1, o2, o3;
        f2unpack(acc[r][0], o0, o1);
        f2unpack(acc[r][1], o2, o3);
        o0 += b0; o1 += b1; o2 += b2; o3 += b3;
        if (act) {
            o0 = __fdividef(o0, 1.f + __expf(-o0));
            o1 = __fdividef(o1, 1.f + __expf(-o1));
            o2 = __fdividef(o2, 1.f + __expf(-o2));
            o3 = __fdividef(o3, 1.f + __expf(-o3));
        }
        *(float4*)&C[(size_t)(by + ty * 8 + r) * N + bx + tx * 4] = make_float4(o0, o1, o2, o3);
    }
}

// ---- L2: hq gemm (0..511) | hist (512..1535) | vt (1536..5631) ----
__global__ void __launch_bounds__(256)
k_L2(const int2* __restrict__ nbrs, const float* __restrict__ v,
     const float* __restrict__ s,
     const float* __restrict__ W1, const float* __restrict__ b1,
     const float* __restrict__ Wd, const float* __restrict__ bd,
     float* __restrict__ h, float* __restrict__ qkv)
{
    __shared__ __align__(16) float As[16][132];
    __shared__ __align__(16) float Bs[16][68];
    const int bid = blockIdx.x, tid = threadIdx.x;
    if (bid < 512) {
        int idx = bid;                          // 0..511
        int bx2 = idx & 7, by = (idx >> 3) * 128;
        if (bx2 < 2)
            gemm_tile(s, W1, b1, h,   128, 1, bx2 * 64,       by, As, Bs);
        else
            gemm_tile(s, Wd, bd, qkv, 384, 0, (bx2 - 2) * 64, by, As, Bs);
    } else if (bid < 1536) {
        int e = (bid - 512) * 256 + tid;
        int2 nb = nbrs[e];
        g_pos[e] = atomicAdd(&g_cnt[nb.x], 1);
    } else {
        int atom = (bid - 1536) * 2 + (tid >> 7);
        int cc = tid & 127;
        const float* p = v + ((size_t)atom * FEAT + cc) * 3;
        float x = p[0], y = p[1], z = p[2];
        g_vt[(size_t)atom * 384 + cc]       = x;
        g_vt[(size_t)atom * 384 + 128 + cc] = y;
        g_vt[(size_t)atom * 384 + 256 + cc] = z;
    }
}

// ---- L3: phi gemm (0..383) | scan (384) ----
__global__ void __launch_bounds__(256)
k_L3(const float* __restrict__ W2, const float* __restrict__ b2)
{
    __shared__ __align__(16) float As[16][132];
    __shared__ __align__(16) float Bs[16][68];
    const int bid = blockIdx.x, t = threadIdx.x;
    if (bid < 384) {
        int idx = bid;                          // 0..383
        int bx = (idx % 6) * 64, by = (idx / 6) * 128;
        gemm_tile(g_h, W2, b2, g_phi, 384, 0, bx, by, As, Bs);
    } else {
        __shared__ int sh[256];
        int c[32];
        int run = 0;
#pragma unroll
        for (int j = 0; j < 32; j++) { int vv = g_cnt[t * 32 + j]; c[j] = run; run += vv; }
        sh[t] = run;
        __syncthreads();
        for (int ofs = 1; ofs < 256; ofs <<= 1) {
            int vv = (t >= ofs) ? sh[t - ofs] : 0;
            __syncthreads();
            sh[t] += vv;
            __syncthreads();
        }
        int excl = sh[t] - run;
#pragma unroll
        for (int j = 0; j < 32; j++) g_off[t * 32 + j] = excl + c[j];
    }
}

// ---- L4: attn (0..127) | scatter (128..1151) ----
#define AT_SMEM 29952
__global__ void __launch_bounds__(256)
k_L4(const int2* __restrict__ nbrs, float* __restrict__ out_s)
{
    extern __shared__ float sm[];
    const int bid = blockIdx.x, tid = threadIdx.x;
    if (bid >= NGRAPHS) {
        int e = (bid - NGRAPHS) * 256 + tid;
        int2 nb = nbrs[e];
        g_eid[g_off[nb.x] + g_pos[e]] = e;
        return;
    }
    const int g = bid;
    float* sQ  = sm;
    float* sKT = sm + 8448;
    float* sV  = sm + 17152;
    float* sP  = sm + 25600;
    const int tx = tid & 15, ty = tid >> 4;

    const float* src = g_qkv + (size_t)g * 64 * 384;
    for (int idx = tid; idx < 64 * 384; idx += 256) {
        int r = idx / 384, col = idx - r * 384;
        float v = src[idx];
        if (col < 128)      sQ[r * 132 + col] = v;
        else if (col < 256) sKT[(col - 128) * 68 + r] = v;
        else                sV[r * 132 + (col - 256)] = v;
    }
    __syncthreads();

    {
        ull sa[4][2];
#pragma unroll
        for (int r = 0; r < 4; r++) { sa[r][0] = 0ull; sa[r][1] = 0ull; }
#pragma unroll 4
        for (int kk = 0; kk < 128; kk++) {
            ull b0 = *(const ull*)&sKT[kk * 68 + tx * 4];
            ull b1 = *(const ull*)&sKT[kk * 68 + tx * 4 + 2];
            float a0 = sQ[(ty * 4 + 0) * 132 + kk];
            float a1 = sQ[(ty * 4 + 1) * 132 + kk];
            float a2 = sQ[(ty * 4 + 2) * 132 + kk];
            float a3 = sQ[(ty * 4 + 3) * 132 + kk];
            ull s;
            s = f2pack(a0, a0); sa[0][0] = f2fma(s, b0, sa[0][0]); sa[0][1] = f2fma(s, b1, sa[0][1]);
            s = f2pack(a1, a1); sa[1][0] = f2fma(s, b0, sa[1][0]); sa[1][1] = f2fma(s, b1, sa[1][1]);
            s = f2pack(a2, a2); sa[2][0] = f2fma(s, b0, sa[2][0]); sa[2][1] = f2fma(s, b1, sa[2][1]);
            s = f2pack(a3, a3); sa[3][0] = f2fma(s, b0, sa[3][0]); sa[3][1] = f2fma(s, b1, sa[3][1]);
        }
        const float scale = 0.08838834764831845f;
#pragma unroll
        for (int r = 0; r < 4; r++) {
            float o0, o1, o2, o3;
            f2unpack(sa[r][0], o0, o1);
            f2unpack(sa[r][1], o2, o3);
            sP[(ty * 4 + r) * 68 + tx * 4 + 0] = o0 * scale;
            sP[(ty * 4 + r) * 68 + tx * 4 + 1] = o1 * scale;
            sP[(ty * 4 + r) * 68 + tx * 4 + 2] = o2 * scale;
            sP[(ty * 4 + r) * 68 + tx * 4 + 3] = o3 * scale;
        }
    }
    __syncthreads();

    if (tid < 64) {
        float* row = sP + tid * 68;
        float mx = row[0];
        for (int j = 1; j < 64; j++) mx = fmaxf(mx, row[j]);
        float sum = 0.f;
        for (int j = 0; j < 64; j++) { float e = __expf(row[j] - mx); row[j] = e; sum += e; }
        float inv = __fdividef(1.f, sum);
        for (int j = 0; j < 64; j++) row[j] *= inv;
    }
    __syncthreads();

    {
        ull aa[4][4];
#pragma unroll
        for (int r = 0; r < 4; r++)
#pragma unroll
            for (int p = 0; p < 4; p++) aa[r][p] = 0ull;
#pragma unroll 4
        for (int kk = 0; kk < 64; kk++) {
            ull b0 = *(const ull*)&sV[kk * 132 + tx * 8];
            ull b1 = *(const ull*)&sV[kk * 132 + tx * 8 + 2];
            ull b2 = *(const ull*)&sV[kk * 132 + tx * 8 + 4];
            ull b3 = *(const ull*)&sV[kk * 132 + tx * 8 + 6];
            float a0 = sP[(ty * 4 + 0) * 68 + kk];
            float a1 = sP[(ty * 4 + 1) * 68 + kk];
            float a2 = sP[(ty * 4 + 2) * 68 + kk];
            float a3 = sP[(ty * 4 + 3) * 68 + kk];
            ull s;
            s = f2pack(a0, a0); aa[0][0]=f2fma(s,b0,aa[0][0]); aa[0][1]=f2fma(s,b1,aa[0][1]); aa[0][2]=f2fma(s,b2,aa[0][2]); aa[0][3]=f2fma(s,b3,aa[0][3]);
            s = f2pack(a1, a1); aa[1][0]=f2fma(s,b0,aa[1][0]); aa[1][1]=f2fma(s,b1,aa[1][1]); aa[1][2]=f2fma(s,b2,aa[1][2]); aa[1][3]=f2fma(s,b3,aa[1][3]);
            s = f2pack(a2, a2); aa[2][0]=f2fma(s,b0,aa[2][0]); aa[2][1]=f2fma(s,b1,aa[2][1]); aa[2][2]=f2fma(s,b2,aa[2][2]); aa[2][3]=f2fma(s,b3,aa[2][3]);
            s = f2pack(a3, a3); aa[3][0]=f2fma(s,b0,aa[3][0]); aa[3][1]=f2fma(s,b1,aa[3][1]); aa[3][2]=f2fma(s,b2,aa[3][2]); aa[3][3]=f2fma(s,b3,aa[3][3]);
        }
#pragma unroll
        for (int r = 0; r < 4; r++) {
            int row = g * 64 + ty * 4 + r;
            float o[8];
            f2unpack(aa[r][0], o[0], o[1]);
            f2unpack(aa[r][1], o[2], o[3]);
            f2unpack(aa[r][2], o[4], o[5]);
            f2unpack(aa[r][3], o[6], o[7]);
            *(float4*)&out_s[(size_t)row * FEAT + tx * 8]     = make_float4(o[0], o[1], o[2], o[3]);
            *(float4*)&out_s[(size_t)row * FEAT + tx * 8 + 4] = make_float4(o[4], o[5], o[6], o[7]);
        }
    }
}

// ---------------- edge message pass (R11 math, vectorized smem reads) --------
__global__ void __launch_bounds__(128, 4)
k_edge(const float* __restrict__ r_ij, const int2* __restrict__ nbrs,
       const float* __restrict__ Wr, const float* __restrict__ br,
       float* __restrict__ out)
{
    const int c = threadIdx.x;

    ull wp0[NRBF / 2], wp1[NRBF / 2], wp2[NRBF / 2];
#pragma unroll
    for (int k = 0; k < NRBF / 2; k++) {
        wp0[k] = f2pack(__ldg(&Wr[(2 * k) * 384 + c]),       __ldg(&Wr[(2 * k + 1) * 384 + c]));
        wp1[k] = f2pack(__ldg(&Wr[(2 * k) * 384 + 128 + c]), __ldg(&Wr[(2 * k + 1) * 384 + 128 + c]));
        wp2[k] = f2pack(__ldg(&Wr[(2 * k) * 384 + 256 + c]), __ldg(&Wr[(2 * k + 1) * 384 + 256 + c]));
    }
    const float br0 = __ldg(&br[c]), br1 = __ldg(&br[128 + c]), br2 = __ldg(&br[256 + c]);

    // st row: t0..t19 | env ux uy uz  (24 floats = 96B, 16B-aligned rows)
    __shared__ __align__(16) float st[32][24];
    __shared__ int sdst[32];

    for (int a = 0; a < APB; a++) {
        const int i = blockIdx.x * APB + a;
        const int deg = g_cnt[i], start = g_off[i];
        float accs = 0.f, avx = 0.f, avy = 0.f, avz = 0.f;

        for (int base = 0; base < deg; base += 32) {
            int m = min(32, deg - base);
            __syncthreads();
            if (c < m) {
                int e = g_eid[start + base + c];
                sdst[c] = nbrs[e].y;
                float rx = r_ij[3 * e], ry = r_ij[3 * e + 1], rz = r_ij[3 * e + 2];
                float d = sqrtf(fmaf(rx, rx, fmaf(ry, ry, rz * rz)));
                bool in = d < 5.0f;
                float invd = in ? __fdividef(1.f, d) : 0.f;
                float s1, c1;
                __sincosf(0.6283185307179586f * d, &s1, &c1);
                float env = in ? fmaf(0.5f, c1, 0.5f) : 0.f;
                float einv = env * invd;
                float c2 = 2.f * c1, sp = 0.f, sc = s1;
                st[c][0] = s1 * einv;
#pragma unroll
                for (int n = 1; n < NRBF; n++) {
                    float sn = fmaf(c2, sc, -sp);
                    sp = sc; sc = sn;
                    st[c][n] = sn * einv;
                }
                *(float4*)&st[c][20] = make_float4(env, rx * invd, ry * invd, rz * invd);
            }
            __syncthreads();
            for (int j = 0; j < m; j++) {
                int dst = sdst[j];
                const float* ph = g_phi + (size_t)dst * 384;
                const float* vt = g_vt + (size_t)dst * 384;
                float ph0 = ph[c], ph1 = ph[c + 128], ph2 = ph[c + 256];
                float vx = vt[c], vy = vt[c + 128], vz = vt[c + 256];
                const ulonglong2* tp2 = (const ulonglong2*)&st[j][0];
                ull tt[10];
#pragma unroll
                for (int q = 0; q < 5; q++) {
                    ulonglong2 u = tp2[q];
                    tt[2 * q] = u.x; tt[2 * q + 1] = u.y;
                }
                float4 tail = *(const float4*)&st[j][20];   // env ux uy uz
                ull w0p = f2mul(tt[0], wp0[0]);
                ull w1p = f2mul(tt[0], wp1[0]);
                ull w2p = f2mul(tt[0], wp2[0]);
#pragma unroll
                for (int k = 1; k < NRBF / 2; k++) {
                    w0p = f2fma(tt[k], wp0[k], w0p);
                    w1p = f2fma(tt[k], wp1[k], w1p);
                    w2p = f2fma(tt[k], wp2[k], w2p);
                }
                float l, h;
                f2unpack(w0p, l, h); float ws0 = fmaf(br0, tail.x, l + h);
                f2unpack(w1p, l, h); float ws1 = fmaf(br1, tail.x, l + h);
                f2unpack(w2p, l, h); float ws2 = fmaf(br2, tail.x, l + h);
                float a0 = ph0 * ws0, a2 = ph2 * ws2;
                accs = fmaf(ph1, ws1, accs);
                avx = fmaf(a2, tail.y, fmaf(a0, vx, avx));
                avy = fmaf(a2, tail.z, fmaf(a0, vy, avy));
                avz = fmaf(a2, tail.w, fmaf(a0, vz, avz));
            }
        }
        size_t idx = (size_t)i * FEAT + c;
        out[idx] += accs;
        float* outv = out + (size_t)NATOMS * FEAT;
        outv[idx * 3 + 0] = avx;
        outv[idx * 3 + 1] = avy;
        outv[idx * 3 + 2] = avz;
    }
}

// ---------------- launch ----------------
extern "C" void kernel_launch(void* const* d_in, const int* in_sizes, int n_in,
                              void* d_out, int out_size)
{
    const float* s_j  = (const float*)d_in[0];
    const float* v_j  = (const float*)d_in[1];
    const float* r_ij = (const float*)d_in[2];
    const int*   nbrs = (const int*)  d_in[3];
    const float* W1 = (const float*)d_in[5];
    const float* b1 = (const float*)d_in[6];
    const float* W2 = (const float*)d_in[7];
    const float* b2 = (const float*)d_in[8];
    const float* Wr = (const float*)d_in[9];
    const float* br = (const float*)d_in[10];
    const float* Wd = (const float*)d_in[11];
    const float* bd = (const float*)d_in[12];
    float* out = (float*)d_out;

    float* g_h_p;   cudaGetSymbolAddress((void**)&g_h_p,   g_h);
    float* g_qkv_p; cudaGetSymbolAddress((void**)&g_qkv_p, g_qkv);
    int*   g_cnt_p; cudaGetSymbolAddress((void**)&g_cnt_p, g_cnt);

    cudaFuncSetAttribute(k_L4, cudaFuncAttributeMaxDynamicSharedMemorySize,
                         AT_SMEM * sizeof(float));

    cudaMemsetAsync(g_cnt_p, 0, NATOMS * sizeof(int));
    k_L2<<<1536 + NATOMS / 2, 256>>>((const int2*)nbrs, v_j, s_j, W1, b1, Wd, bd,
                                     g_h_p, g_qkv_p);
    k_L3<<<384 + 1, 256>>>(W2, b2);
    k_L4<<<NGRAPHS + 1024, 256, AT_SMEM * sizeof(float)>>>((const int2*)nbrs, out);
    k_edge<<<NATOMS / APB, 128>>>(r_ij, (const int2*)nbrs, Wr, br, out);
}

// round 17
// speedup vs baseline: 1.0268x; 1.0268x over previous
#include <cuda_runtime.h>
#include <math.h>

#define FEAT    128
#define NRBF    20
#define NATOMS  8192
#define NEDGES  262144
#define NGRAPHS 128
#define APB     8

typedef unsigned long long ull;

// ---------------- f32x2 packed helpers ----------------
__device__ __forceinline__ ull f2pack(float lo, float hi) {
    ull r; asm("mov.b64 %0,{%1,%2};" : "=l"(r) : "f"(lo), "f"(hi)); return r;
}
__device__ __forceinline__ void f2unpack(ull p, float& a, float& b) {
    asm("mov.b64 {%0,%1},%2;" : "=f"(a), "=f"(b) : "l"(p));
}
__device__ __forceinline__ ull f2fma(ull a, ull b, ull c) {
    ull d; asm("fma.rn.f32x2 %0,%1,%2,%3;" : "=l"(d) : "l"(a), "l"(b), "l"(c)); return d;
}
__device__ __forceinline__ ull f2mul(ull a, ull b) {
    ull d; asm("mul.rn.f32x2 %0,%1,%2;" : "=l"(d) : "l"(a), "l"(b)); return d;
}

// ---------------- device scratch ----------------
__device__ float g_phi[NATOMS * 384];
__device__ float g_qkv[NATOMS * 384];
__device__ float g_h  [NATOMS * 128];
__device__ float g_vt [NATOMS * 384];
__device__ int   g_cnt[NATOMS];
__device__ int   g_off[NATOMS];
__device__ int   g_pos[NEDGES];
__device__ int   g_eid[NEDGES];

// ------- SGEMM 128x64 tile, 8x4 per thread, f32x2, K=128, k-step 32 ---------
__device__ __forceinline__ void gemm_tile(
    const float* __restrict__ A, const float* __restrict__ B,
    const float* __restrict__ bias, float* __restrict__ C,
    int N, int act, int bx, int by,
    float As[32][132], float Bs[32][68])
{
    const int tid = threadIdx.x;
    const int tx = tid & 15, ty = tid >> 4;
    const int ar = tid >> 1, aq = (tid & 1) * 16;  // A loader: row, 16-float half-row
    const int bk = tid >> 4, bc = (tid & 15) * 4;  // B loader: k-row (and +16), col quad

    ull acc[8][2];
#pragma unroll
    for (int r = 0; r < 8; r++) { acc[r][0] = 0ull; acc[r][1] = 0ull; }

    for (int k0 = 0; k0 < 128; k0 += 32) {
        __syncthreads();
        {
            const float* arow = &A[(size_t)(by + ar) * 128 + k0 + aq];
            float4 a0 = *(const float4*)(arow);
            float4 a1 = *(const float4*)(arow + 4);
            float4 a2 = *(const float4*)(arow + 8);
            float4 a3 = *(const float4*)(arow + 12);
            As[aq + 0][ar] = a0.x;  As[aq + 1][ar] = a0.y;
            As[aq + 2][ar] = a0.z;  As[aq + 3][ar] = a0.w;
            As[aq + 4][ar] = a1.x;  As[aq + 5][ar] = a1.y;
            As[aq + 6][ar] = a1.z;  As[aq + 7][ar] = a1.w;
            As[aq + 8][ar] = a2.x;  As[aq + 9][ar] = a2.y;
            As[aq + 10][ar] = a2.z; As[aq + 11][ar] = a2.w;
            As[aq + 12][ar] = a3.x; As[aq + 13][ar] = a3.y;
            As[aq + 14][ar] = a3.z; As[aq + 15][ar] = a3.w;
            *(float4*)&Bs[bk][bc]      = *(const float4*)&B[(size_t)(k0 + bk) * N + bx + bc];
            *(float4*)&Bs[bk + 16][bc] = *(const float4*)&B[(size_t)(k0 + bk + 16) * N + bx + bc];
        }
        __syncthreads();
#pragma unroll
        for (int kk = 0; kk < 32; kk++) {
            float4 x0 = *(const float4*)&As[kk][ty * 8];
            float4 x1 = *(const float4*)&As[kk][ty * 8 + 4];
            ull b0 = *(const ull*)&Bs[kk][tx * 4];
            ull b1 = *(const ull*)&Bs[kk][tx * 4 + 2];
            float av[8] = {x0.x, x0.y, x0.z, x0.w, x1.x, x1.y, x1.z, x1.w};
#pragma unroll
            for (int r = 0; r < 8; r++) {
                ull s = f2pack(av[r], av[r]);
                acc[r][0] = f2fma(s, b0, acc[r][0]);
                acc[r][1] = f2fma(s, b1, acc[r][1]);
            }
        }
    }
    float b0 = bias[bx + tx * 4], b1 = bias[bx + tx * 4 + 1];
    float b2 = bias[bx + tx * 4 + 2], b3 = bias[bx + tx * 4 + 3];
#pragma unroll
    for (int r = 0; r < 8; r++) {
        float o0, o1, o2, o3;
        f2unpack(acc[r][0], o0, o1);
        f2unpack(acc[r][1], o2, o3);
        o0 += b0; o1 += b1; o2 += b2; o3 += b3;
        if (act) {
            o0 = __fdividef(o0, 1.f + __expf(-o0));
            o1 = __fdividef(o1, 1.f + __expf(-o1));
            o2 = __fdividef(o2, 1.f + __expf(-o2));
            o3 = __fdividef(o3, 1.f + __expf(-o3));
        }
        *(float4*)&C[(size_t)(by + ty * 8 + r) * N + bx + tx * 4] = make_float4(o0, o1, o2, o3);
    }
}

// ---- L2: hq gemm (0..511) | hist (512..1535) | vt (1536..5631) ----
__global__ void __launch_bounds__(256)
k_L2(const int2* __restrict__ nbrs, const float* __restrict__ v,
     const float* __restrict__ s,
     const float* __restrict__ W1, const float* __restrict__ b1,
     const float* __restrict__ Wd, const float* __restrict__ bd,
     float* __restrict__ h, float* __restrict__ qkv)
{
    __shared__ __align__(16) float As[32][132];
    __shared__ __align__(16) float Bs[32][68];
    const int bid = blockIdx.x, tid = threadIdx.x;
    if (bid < 512) {
        int idx = bid;                          // 0..511
        int bx2 = idx & 7, by = (idx >> 3) * 128;
        if (bx2 < 2)
            gemm_tile(s, W1, b1, h,   128, 1, bx2 * 64,       by, As, Bs);
        else
            gemm_tile(s, Wd, bd, qkv, 384, 0, (bx2 - 2) * 64, by, As, Bs);
    } else if (bid < 1536) {
        int e = (bid - 512) * 256 + tid;
        int2 nb = nbrs[e];
        g_pos[e] = atomicAdd(&g_cnt[nb.x], 1);
    } else {
        int atom = (bid - 1536) * 2 + (tid >> 7);
        int cc = tid & 127;
        const float* p = v + ((size_t)atom * FEAT + cc) * 3;
        float x = p[0], y = p[1], z = p[2];
        g_vt[(size_t)atom * 384 + cc]       = x;
        g_vt[(size_t)atom * 384 + 128 + cc] = y;
        g_vt[(size_t)atom * 384 + 256 + cc] = z;
    }
}

// ---- L3: phi gemm (0..383) | scan (384) ----
__global__ void __launch_bounds__(256)
k_L3(const float* __restrict__ W2, const float* __restrict__ b2)
{
    __shared__ __align__(16) float As[32][132];
    __shared__ __align__(16) float Bs[32][68];
    const int bid = blockIdx.x, t = threadIdx.x;
    if (bid < 384) {
        int idx = bid;                          // 0..383
        int bx = (idx % 6) * 64, by = (idx / 6) * 128;
        gemm_tile(g_h, W2, b2, g_phi, 384, 0, bx, by, As, Bs);
    } else {
        __shared__ int sh[256];
        int c[32];
        int run = 0;
#pragma unroll
        for (int j = 0; j < 32; j++) { int vv = g_cnt[t * 32 + j]; c[j] = run; run += vv; }
        sh[t] = run;
        __syncthreads();
        for (int ofs = 1; ofs < 256; ofs <<= 1) {
            int vv = (t >= ofs) ? sh[t - ofs] : 0;
            __syncthreads();
            sh[t] += vv;
            __syncthreads();
        }
        int excl = sh[t] - run;
#pragma unroll
        for (int j = 0; j < 32; j++) g_off[t * 32 + j] = excl + c[j];
    }
}

// ---- L4: attn (0..127) | scatter (128..1151) ----
#define AT_SMEM 29952
__global__ void __launch_bounds__(256)
k_L4(const int2* __restrict__ nbrs, float* __restrict__ out_s)
{
    extern __shared__ float sm[];
    const int bid = blockIdx.x, tid = threadIdx.x;
    if (bid >= NGRAPHS) {
        int e = (bid - NGRAPHS) * 256 + tid;
        int2 nb = nbrs[e];
        g_eid[g_off[nb.x] + g_pos[e]] = e;
        return;
    }
    const int g = bid;
    float* sQ  = sm;
    float* sKT = sm + 8448;
    float* sV  = sm + 17152;
    float* sP  = sm + 25600;
    const int tx = tid & 15, ty = tid >> 4;

    const float* src = g_qkv + (size_t)g * 64 * 384;
    for (int idx = tid; idx < 64 * 384; idx += 256) {
        int r = idx / 384, col = idx - r * 384;
        float v = src[idx];
        if (col < 128)      sQ[r * 132 + col] = v;
        else if (col < 256) sKT[(col - 128) * 68 + r] = v;
        else                sV[r * 132 + (col - 256)] = v;
    }
    __syncthreads();

    {
        ull sa[4][2];
#pragma unroll
        for (int r = 0; r < 4; r++) { sa[r][0] = 0ull; sa[r][1] = 0ull; }
#pragma unroll 4
        for (int kk = 0; kk < 128; kk++) {
            ull b0 = *(const ull*)&sKT[kk * 68 + tx * 4];
            ull b1 = *(const ull*)&sKT[kk * 68 + tx * 4 + 2];
            float a0 = sQ[(ty * 4 + 0) * 132 + kk];
            float a1 = sQ[(ty * 4 + 1) * 132 + kk];
            float a2 = sQ[(ty * 4 + 2) * 132 + kk];
            float a3 = sQ[(ty * 4 + 3) * 132 + kk];
            ull s;
            s = f2pack(a0, a0); sa[0][0] = f2fma(s, b0, sa[0][0]); sa[0][1] = f2fma(s, b1, sa[0][1]);
            s = f2pack(a1, a1); sa[1][0] = f2fma(s, b0, sa[1][0]); sa[1][1] = f2fma(s, b1, sa[1][1]);
            s = f2pack(a2, a2); sa[2][0] = f2fma(s, b0, sa[2][0]); sa[2][1] = f2fma(s, b1, sa[2][1]);
            s = f2pack(a3, a3); sa[3][0] = f2fma(s, b0, sa[3][0]); sa[3][1] = f2fma(s, b1, sa[3][1]);
        }
        const float scale = 0.08838834764831845f;
#pragma unroll
        for (int r = 0; r < 4; r++) {
            float o0, o1, o2, o3;
            f2unpack(sa[r][0], o0, o1);
            f2unpack(sa[r][1], o2, o3);
            sP[(ty * 4 + r) * 68 + tx * 4 + 0] = o0 * scale;
            sP[(ty * 4 + r) * 68 + tx * 4 + 1] = o1 * scale;
            sP[(ty * 4 + r) * 68 + tx * 4 + 2] = o2 * scale;
            sP[(ty * 4 + r) * 68 + tx * 4 + 3] = o3 * scale;
        }
    }
    __syncthreads();

    if (tid < 64) {
        float* row = sP + tid * 68;
        float mx = row[0];
        for (int j = 1; j < 64; j++) mx = fmaxf(mx, row[j]);
        float sum = 0.f;
        for (int j = 0; j < 64; j++) { float e = __expf(row[j] - mx); row[j] = e; sum += e; }
        float inv = __fdividef(1.f, sum);
        for (int j = 0; j < 64; j++) row[j] *= inv;
    }
    __syncthreads();

    {
        ull aa[4][4];
#pragma unroll
        for (int r = 0; r < 4; r++)
#pragma unroll
            for (int p = 0; p < 4; p++) aa[r][p] = 0ull;
#pragma unroll 4
        for (int kk = 0; kk < 64; kk++) {
            ull b0 = *(const ull*)&sV[kk * 132 + tx * 8];
            ull b1 = *(const ull*)&sV[kk * 132 + tx * 8 + 2];
            ull b2 = *(const ull*)&sV[kk * 132 + tx * 8 + 4];
            ull b3 = *(const ull*)&sV[kk * 132 + tx * 8 + 6];
            float a0 = sP[(ty * 4 + 0) * 68 + kk];
            float a1 = sP[(ty * 4 + 1) * 68 + kk];
            float a2 = sP[(ty * 4 + 2) * 68 + kk];
            float a3 = sP[(ty * 4 + 3) * 68 + kk];
            ull s;
            s = f2pack(a0, a0); aa[0][0]=f2fma(s,b0,aa[0][0]); aa[0][1]=f2fma(s,b1,aa[0][1]); aa[0][2]=f2fma(s,b2,aa[0][2]); aa[0][3]=f2fma(s,b3,aa[0][3]);
            s = f2pack(a1, a1); aa[1][0]=f2fma(s,b0,aa[1][0]); aa[1][1]=f2fma(s,b1,aa[1][1]); aa[1][2]=f2fma(s,b2,aa[1][2]); aa[1][3]=f2fma(s,b3,aa[1][3]);
            s = f2pack(a2, a2); aa[2][0]=f2fma(s,b0,aa[2][0]); aa[2][1]=f2fma(s,b1,aa[2][1]); aa[2][2]=f2fma(s,b2,aa[2][2]); aa[2][3]=f2fma(s,b3,aa[2][3]);
            s = f2pack(a3, a3); aa[3][0]=f2fma(s,b0,aa[3][0]); aa[3][1]=f2fma(s,b1,aa[3][1]); aa[3][2]=f2fma(s,b2,aa[3][2]); aa[3][3]=f2fma(s,b3,aa[3][3]);
        }
#pragma unroll
        for (int r = 0; r < 4; r++) {
            int row = g * 64 + ty * 4 + r;
            float o[8];
            f2unpack(aa[r][0], o[0], o[1]);
            f2unpack(aa[r][1], o[2], o[3]);
            f2unpack(aa[r][2], o[4], o[5]);
            f2unpack(aa[r][3], o[6], o[7]);
            *(float4*)&out_s[(size_t)row * FEAT + tx * 8]     = make_float4(o[0], o[1], o[2], o[3]);
            *(float4*)&out_s[(size_t)row * FEAT + tx * 8 + 4] = make_float4(o[4], o[5], o[6], o[7]);
        }
    }
}

// ---------------- edge message pass (R11/R15 form — verbatim) ----------------
__global__ void __launch_bounds__(128, 4)
k_edge(const float* __restrict__ r_ij, const int2* __restrict__ nbrs,
       const float* __restrict__ Wr, const float* __restrict__ br,
       float* __restrict__ out)
{
    const int c = threadIdx.x;

    ull wp0[NRBF / 2], wp1[NRBF / 2], wp2[NRBF / 2];
#pragma unroll
    for (int k = 0; k < NRBF / 2; k++) {
        wp0[k] = f2pack(__ldg(&Wr[(2 * k) * 384 + c]),       __ldg(&Wr[(2 * k + 1) * 384 + c]));
        wp1[k] = f2pack(__ldg(&Wr[(2 * k) * 384 + 128 + c]), __ldg(&Wr[(2 * k + 1) * 384 + 128 + c]));
        wp2[k] = f2pack(__ldg(&Wr[(2 * k) * 384 + 256 + c]), __ldg(&Wr[(2 * k + 1) * 384 + 256 + c]));
    }
    const float br0 = __ldg(&br[c]), br1 = __ldg(&br[128 + c]), br2 = __ldg(&br[256 + c]);

    __shared__ __align__(16) float st[32][NRBF];
    __shared__ float senv[32], sux[32], suy[32], suz[32];
    __shared__ int sdst[32];

    for (int a = 0; a < APB; a++) {
        const int i = blockIdx.x * APB + a;
        const int deg = g_cnt[i], start = g_off[i];
        float accs = 0.f, avx = 0.f, avy = 0.f, avz = 0.f;

        for (int base = 0; base < deg; base += 32) {
            int m = min(32, deg - base);
            __syncthreads();
            if (c < m) {
                int e = g_eid[start + base + c];
                sdst[c] = nbrs[e].y;
                float rx = r_ij[3 * e], ry = r_ij[3 * e + 1], rz = r_ij[3 * e + 2];
                float d = sqrtf(fmaf(rx, rx, fmaf(ry, ry, rz * rz)));
                bool in = d < 5.0f;
                float invd = in ? __fdividef(1.f, d) : 0.f;
                float s1, c1;
                __sincosf(0.6283185307179586f * d, &s1, &c1);
                float env = in ? fmaf(0.5f, c1, 0.5f) : 0.f;
                float einv = env * invd;
                senv[c] = env;
                sux[c] = rx * invd; suy[c] = ry * invd; suz[c] = rz * invd;
                float c2 = 2.f * c1, sp = 0.f, sc = s1;
                st[c][0] = s1 * einv;
#pragma unroll
                for (int n = 1; n < NRBF; n++) {
                    float sn = fmaf(c2, sc, -sp);
                    sp = sc; sc = sn;
                    st[c][n] = sn * einv;
                }
            }
            __syncthreads();
            for (int j = 0; j < m; j++) {
                int dst = sdst[j];
                const float* ph = g_phi + (size_t)dst * 384;
                const float* vt = g_vt + (size_t)dst * 384;
                float ph0 = ph[c], ph1 = ph[c + 128], ph2 = ph[c + 256];
                float vx = vt[c], vy = vt[c + 128], vz = vt[c + 256];
                float env = senv[j], ux = sux[j], uy = suy[j], uz = suz[j];
                const ull* tp = (const ull*)&st[j][0];
                ull t = tp[0];
                ull w0p = f2mul(t, wp0[0]);
                ull w1p = f2mul(t, wp1[0]);
                ull w2p = f2mul(t, wp2[0]);
#pragma unroll
                for (int k = 1; k < NRBF / 2; k++) {
                    t = tp[k];
                    w0p = f2fma(t, wp0[k], w0p);
                    w1p = f2fma(t, wp1[k], w1p);
                    w2p = f2fma(t, wp2[k], w2p);
                }
                float l, h;
                f2unpack(w0p, l, h); float ws0 = fmaf(br0, env, l + h);
                f2unpack(w1p, l, h); float ws1 = fmaf(br1, env, l + h);
                f2unpack(w2p, l, h); float ws2 = fmaf(br2, env, l + h);
                float a0 = ph0 * ws0, a2 = ph2 * ws2;
                accs = fmaf(ph1, ws1, accs);
                avx = fmaf(a2, ux, fmaf(a0, vx, avx));
                avy = fmaf(a2, uy, fmaf(a0, vy, avy));
                avz = fmaf(a2, uz, fmaf(a0, vz, avz));
            }
        }
        size_t idx = (size_t)i * FEAT + c;
        out[idx] += accs;
        float* outv = out + (size_t)NATOMS * FEAT;
        outv[idx * 3 + 0] = avx;
        outv[idx * 3 + 1] = avy;
        outv[idx * 3 + 2] = avz;
    }
}

// ---------------- launch ----------------
extern "C" void kernel_launch(void* const* d_in, const int* in_sizes, int n_in,
                              void* d_out, int out_size)
{
    const float* s_j  = (const float*)d_in[0];
    const float* v_j  = (const float*)d_in[1];
    const float* r_ij = (const float*)d_in[2];
    const int*   nbrs = (const int*)  d_in[3];
    const float* W1 = (const float*)d_in[5];
    const float* b1 = (const float*)d_in[6];
    const float* W2 = (const float*)d_in[7];
    const float* b2 = (const float*)d_in[8];
    const float* Wr = (const float*)d_in[9];
    const float* br = (const float*)d_in[10];
    const float* Wd = (const float*)d_in[11];
    const float* bd = (const float*)d_in[12];
    float* out = (float*)d_out;

    float* g_h_p;   cudaGetSymbolAddress((void**)&g_h_p,   g_h);
    float* g_qkv_p; cudaGetSymbolAddress((void**)&g_qkv_p, g_qkv);
    int*   g_cnt_p; cudaGetSymbolAddress((void**)&g_cnt_p, g_cnt);

    cudaFuncSetAttribute(k_L4, cudaFuncAttributeMaxDynamicSharedMemorySize,
                         AT_SMEM * sizeof(float));

    cudaMemsetAsync(g_cnt_p, 0, NATOMS * sizeof(int));
    k_L2<<<1536 + NATOMS / 2, 256>>>((const int2*)nbrs, v_j, s_j, W1, b1, Wd, bd,
                                     g_h_p, g_qkv_p);
    k_L3<<<384 + 1, 256>>>(W2, b2);
    k_L4<<<NGRAPHS + 1024, 256, AT_SMEM * sizeof(float)>>>((const int2*)nbrs, out);
    k_edge<<<NATOMS / APB, 128>>>(r_ij, (const int2*)nbrs, Wr, br, out);
}